// round 13
// baseline (speedup 1.0000x reference)
#include <cuda_runtime.h>
#include <cuda_fp16.h>
#include <math.h>
#include <cstdint>

#define BATCH 32
#define SEQ   256
#define HID   768

#define NTP 512                 // 16 warps = 4 (m-rows) x 4 (n-cols)
#define KC  64                  // fp16 elems per K chunk (128B rows)
#define NCH (HID / KC)          // 12 chunks
#define NSTG 3                  // pipeline stages
#define ROWB 144                // 128B data + 16B pad

// smem layout (dynamic)
#define SM_WD    0
#define SM_KV    1024
#define SM_RED   2048
#define SM_SMAX  2112           // [128][4]
#define SM_SZ    4160
#define SM_SS    6208
#define SM_TILES 8448
#define OFF_A    0              // 128 rows * 144B = 18432
#define OFF_B    18432          // 256 rows * 144B = 36864
#define BUFSZ    55296
#define SMEM_TOTAL (SM_TILES + NSTG * BUFSZ)   // 174336

#define NEG_HUGE (-3.402823466e38f)

// Scratch (allocation-free rule: __device__ globals)
__device__ __half g_qh[BATCH * SEQ * HID];   // fp16(q_norm)
__device__ __half g_kh[BATCH * SEQ * HID];   // fp16(k_norm)
__device__ float  g_wd[SEQ];
__device__ float  g_invden[BATCH];

__device__ __forceinline__ uint32_t smem_u32(const void* p) {
    uint32_t a;
    asm("{ .reg .u64 t; cvta.to.shared.u64 t, %1; cvt.u32.u64 %0, t; }" : "=r"(a) : "l"(p));
    return a;
}

#define LDSM4(A, addr)                                                          \
    asm volatile("ldmatrix.sync.aligned.m8n8.x4.shared.b16 {%0,%1,%2,%3}, [%4];"\
        : "=r"((A)[0]), "=r"((A)[1]), "=r"((A)[2]), "=r"((A)[3]) : "r"(addr))

#define LDSB32(r, addr) \
    asm volatile("ld.shared.b32 %0, [%1];" : "=r"(r) : "r"(addr))

#define MMAH(acc, A, b0, b1)                                                    \
    asm volatile("mma.sync.aligned.m16n8k16.row.col.f32.f16.f16.f32 "           \
        "{%0,%1,%2,%3}, {%4,%5,%6,%7}, {%8,%9}, {%0,%1,%2,%3};"                 \
        : "+f"((acc)[0]), "+f"((acc)[1]), "+f"((acc)[2]), "+f"((acc)[3])        \
        : "r"((A)[0]), "r"((A)[1]), "r"((A)[2]), "r"((A)[3]), "r"(b0), "r"(b1))

#define CP16(d, s) \
    asm volatile("cp.async.cg.shared.global [%0], [%1], 16;" :: "r"(d), "l"(s) : "memory")
#define CPCOMMIT() asm volatile("cp.async.commit_group;" ::: "memory")
#define CPWAIT(n)  asm volatile("cp.async.wait_group %0;" :: "n"(n) : "memory")

// ---------------------------------------------------------------------------
// Kernel 1: L2-normalize q,k -> fp16; extra block (last) computes decay
// table + inverse denominators and zeroes the output accumulator.
// ---------------------------------------------------------------------------
__global__ void quant_kernel(const float* __restrict__ q,
                             const float* __restrict__ k,
                             const float* __restrict__ qmask,
                             const float* __restrict__ alpha_raw,
                             const float* __restrict__ logit_scale,
                             float* __restrict__ out) {
    int row = blockIdx.x;
    int t = threadIdx.x;

    if (row == 2 * BATCH * SEQ) {   // tables + output zeroing block
        float a = *alpha_raw;
        float alpha = (a > 20.f) ? a : log1pf(expf(a));
        float scale = expf(*logit_scale);
        g_wd[t] = scale * expf(-alpha * (float)t);
        if (t < BATCH) {
            float s = 0.f;
            for (int x = 0; x < SEQ; x++) s += qmask[t * SEQ + x];
            g_invden[t] = 1.0f / fmaxf(s, 1.0f);
        }
        out[t] = 0.f; out[t + 256] = 0.f; out[t + 512] = 0.f; out[t + 768] = 0.f;
        return;
    }

    const bool is_q = (row < BATCH * SEQ);
    int r = is_q ? row : row - BATCH * SEQ;
    const float* src = (is_q ? q : k) + (size_t)r * HID;
    __half* dh = (is_q ? g_qh : g_kh) + (size_t)r * HID;
    float v0 = src[t], v1 = src[t + 256], v2 = src[t + 512];
    float ss = v0 * v0 + v1 * v1 + v2 * v2;
#pragma unroll
    for (int o = 16; o > 0; o >>= 1) ss += __shfl_xor_sync(0xFFFFFFFFu, ss, o);
    __shared__ float sred[8];
    __shared__ float s_inv;
    if ((t & 31) == 0) sred[t >> 5] = ss;
    __syncthreads();
    if (t == 0) {
        float tot = 0.f;
#pragma unroll
        for (int w = 0; w < 8; w++) tot += sred[w];
        s_inv = 1.0f / fmaxf(sqrtf(tot), 1e-12f);
    }
    __syncthreads();
    float inv = s_inv;
    dh[t]       = __float2half(v0 * inv);
    dh[t + 256] = __float2half(v1 * inv);
    dh[t + 512] = __float2half(v2 * inv);
}

// ---------------------------------------------------------------------------
// Kernel 2: per-(pair, s-half) fp16 MMA GEMM sim = hq . hk, 128x256 tile,
// warp tile 32x64, 3-stage cp.async ring, one barrier per chunk, fused
// decay + masked softmax epilogue, atomic accumulation into out[pair].
// ---------------------------------------------------------------------------
__global__ __launch_bounds__(NTP, 1)
void pair_kernel(const float* __restrict__ qmask,
                 const float* __restrict__ kmask,
                 float* __restrict__ out) {
    extern __shared__ char smem[];
    const uint32_t sb = smem_u32(smem);
    float* s_wd  = (float*)(smem + SM_WD);
    float* s_kv  = (float*)(smem + SM_KV);
    float* s_red = (float*)(smem + SM_RED);
    float* stg_max = (float*)(smem + SM_SMAX);
    float* stg_z   = (float*)(smem + SM_SZ);
    float* stg_s   = (float*)(smem + SM_SS);

    const int tid = threadIdx.x;
    const int w = tid >> 5, lane = tid & 31;
    const int wr = w >> 2, wc = w & 3;
    const int bx = blockIdx.x;
    const int pair = bx >> 1, shalf = bx & 1;
    const int i = pair >> 5, j = pair & 31;
    const int s0 = shalf * 128;

    const __half* Ag = g_qh + ((size_t)i * SEQ + s0) * HID;
    const __half* Bg = g_kh + (size_t)j * SEQ * HID;

    if (tid < SEQ) {
        s_wd[tid] = g_wd[tid];
        s_kv[tid] = (kmask[j * SEQ + tid] > 0.f) ? 1.f : 0.f;
    }

    float acc[2][8][4];
#pragma unroll
    for (int mi = 0; mi < 2; mi++)
#pragma unroll
        for (int ni = 0; ni < 8; ni++)
#pragma unroll
            for (int e = 0; e < 4; e++) acc[mi][ni][e] = 0.f;

    // cp.async one chunk (A 16KB + B 32KB) into stage cc%NSTG
    auto issue = [&](int cc) {
        const int kcol = cc * KC;
        const uint32_t tb = sb + SM_TILES + (cc % NSTG) * BUFSZ;
#pragma unroll
        for (int qq = 0; qq < 2; qq++) {   // A: 128 rows x 8 groups = 1024 x 16B
            int idx = qq * NTP + tid;
            int row = idx >> 3, g = idx & 7;
            CP16(tb + OFF_A + row * ROWB + g * 16,
                 Ag + (size_t)row * HID + kcol + g * 8);
        }
#pragma unroll
        for (int qq = 0; qq < 4; qq++) {   // B: 256 rows x 8 groups = 2048 x 16B
            int idx = qq * NTP + tid;
            int row = idx >> 3, g = idx & 7;
            CP16(tb + OFF_B + row * ROWB + g * 16,
                 Bg + (size_t)row * HID + kcol + g * 8);
        }
        CPCOMMIT();
    };

    issue(0);
    issue(1);

    const uint32_t lrow = lane & 15, lk16 = (lane >> 4) * 16;
    const uint32_t bln = (lane >> 2), blc = (lane & 3) * 4;

    for (int cc = 0; cc < NCH; cc++) {
        CPWAIT(1);           // group cc complete (own thread)
        __syncthreads();     // visibility + all warps done with MMA(cc-1)
        if (cc + 2 < NCH) issue(cc + 2);   // overlaps MMA below

        const uint32_t tb = sb + SM_TILES + (cc % NSTG) * BUFSZ;
#pragma unroll
        for (int k16 = 0; k16 < 4; k16++) {
            uint32_t af[2][4];
            uint32_t koff = k16 * 32 + lk16;
#pragma unroll
            for (int mi = 0; mi < 2; mi++) {
                uint32_t row = wr * 32 + mi * 16 + lrow;
                LDSM4(af[mi], tb + OFF_A + row * ROWB + koff);
            }
#pragma unroll
            for (int ni = 0; ni < 8; ni++) {
                uint32_t n = wc * 64 + ni * 8 + bln;
                uint32_t ba = tb + OFF_B + n * ROWB + k16 * 32 + blc;
                uint32_t b0, b1;
                LDSB32(b0, ba);
                LDSB32(b1, ba + 16);
                MMAH(acc[0][ni], af[0], b0, b1);
                MMAH(acc[1][ni], af[1], b0, b1);
            }
        }
    }
    __syncthreads();   // last buffer consumed by all before epilogue smem reuse

    // ---- epilogue: decay + masked softmax over t, score = sum p*sim ------
    // Fast path: wd[0] = scale is the max decay weight and |sim| <= ~1.01,
    // so when scale <= 60 no exp can overflow -> skip the row-max stage.
    const bool fast = (s_wd[0] <= 60.0f);

    if (!fast) {
        // stage 1: per-row max over this warp's 64 cols
#pragma unroll
        for (int mi = 0; mi < 2; mi++)
#pragma unroll
            for (int q8 = 0; q8 < 2; q8++) {
                int r = wr * 32 + mi * 16 + q8 * 8 + (lane >> 2);
                int sg = s0 + r;
                float m = NEG_HUGE;
#pragma unroll
                for (int ni = 0; ni < 8; ni++)
#pragma unroll
                    for (int e = 0; e < 2; e++) {
                        int t = wc * 64 + ni * 8 + 2 * (lane & 3) + e;
                        float v = acc[mi][ni][q8 * 2 + e];
                        int d = sg - t; d = (d < 0) ? -d : d;
                        float l = v * s_wd[d];
                        if (s_kv[t] > 0.f) m = fmaxf(m, l);
                    }
                m = fmaxf(m, __shfl_xor_sync(0xFFFFFFFFu, m, 1));
                m = fmaxf(m, __shfl_xor_sync(0xFFFFFFFFu, m, 2));
                if ((lane & 3) == 0) stg_max[r * 4 + wc] = m;
            }
        __syncthreads();
    }

    // stage 2: exp-sum and weighted sim-sum
#pragma unroll
    for (int mi = 0; mi < 2; mi++)
#pragma unroll
        for (int q8 = 0; q8 < 2; q8++) {
            int r = wr * 32 + mi * 16 + q8 * 8 + (lane >> 2);
            int sg = s0 + r;
            float M = 0.f;
            bool mvalid = true;
            if (!fast) {
                M = fmaxf(fmaxf(stg_max[r * 4], stg_max[r * 4 + 1]),
                          fmaxf(stg_max[r * 4 + 2], stg_max[r * 4 + 3]));
                mvalid = (M > NEG_HUGE);
            }
            float Z = 0.f, S = 0.f;
#pragma unroll
            for (int ni = 0; ni < 8; ni++)
#pragma unroll
                for (int e = 0; e < 2; e++) {
                    int t = wc * 64 + ni * 8 + 2 * (lane & 3) + e;
                    float v = acc[mi][ni][q8 * 2 + e];
                    int d = sg - t; d = (d < 0) ? -d : d;
                    float l = v * s_wd[d];
                    float ex = (s_kv[t] > 0.f && mvalid) ? __expf(l - M) : 0.f;
                    Z += ex; S += ex * v;
                }
            Z += __shfl_xor_sync(0xFFFFFFFFu, Z, 1);
            Z += __shfl_xor_sync(0xFFFFFFFFu, Z, 2);
            S += __shfl_xor_sync(0xFFFFFFFFu, S, 1);
            S += __shfl_xor_sync(0xFFFFFFFFu, S, 2);
            if ((lane & 3) == 0) { stg_z[r * 4 + wc] = Z; stg_s[r * 4 + wc] = S; }
        }
    __syncthreads();

    // stage 3: combine warp-cols, apply q_mask, block-reduce, atomic out
    float val = 0.f;
    if (tid < 128) {
        int r = tid;
        float Z = stg_z[r * 4] + stg_z[r * 4 + 1] + stg_z[r * 4 + 2] + stg_z[r * 4 + 3];
        float S = stg_s[r * 4] + stg_s[r * 4 + 1] + stg_s[r * 4 + 2] + stg_s[r * 4 + 3];
        float sc = (Z > 0.f) ? (S / Z) : 0.f;
        val = sc * qmask[i * SEQ + s0 + r];
    }
#pragma unroll
    for (int o = 16; o > 0; o >>= 1) val += __shfl_xor_sync(0xFFFFFFFFu, val, o);
    if (tid < 128 && lane == 0) s_red[w] = val;
    __syncthreads();
    if (tid == 0) {
        float tot = s_red[0] + s_red[1] + s_red[2] + s_red[3];
        atomicAdd(&out[pair], tot * g_invden[i]);   // 2 commutative addends: deterministic
    }
}

// ---------------------------------------------------------------------------
extern "C" void kernel_launch(void* const* d_in, const int* in_sizes, int n_in,
                              void* d_out, int out_size) {
    const float* q  = (const float*)d_in[0];
    const float* k  = (const float*)d_in[1];
    const float* qm = (const float*)d_in[2];
    const float* km = (const float*)d_in[3];
    const float* ar = (const float*)d_in[4];
    const float* ls = (const float*)d_in[5];
    float* out = (float*)d_out;

    static int attr_done = 0;
    if (!attr_done) {
        cudaFuncSetAttribute(pair_kernel, cudaFuncAttributeMaxDynamicSharedMemorySize, SMEM_TOTAL);
        attr_done = 1;
    }

    quant_kernel<<<2 * BATCH * SEQ + 1, 256>>>(q, k, qm, ar, ls, out);
    pair_kernel<<<BATCH * BATCH * 2, NTP, SMEM_TOTAL>>>(qm, km, out);
}

// round 16
// speedup vs baseline: 1.0771x; 1.0771x over previous
#include <cuda_runtime.h>
#include <cuda_fp16.h>
#include <math.h>
#include <cstdint>

#define BATCH 32
#define SEQ   256
#define HID   768

#define NTP 512                 // 16 warps = 4 (m-rows) x 4 (n-cols)
#define KC  64                  // fp16 elems per K chunk (128B rows)
#define NCH (HID / KC)          // 12 chunks
#define NSTG 3                  // pipeline stages
#define ROWB 144                // 128B data + 16B pad

// smem layout (dynamic)
#define SM_WD    0
#define SM_KV    1024
#define SM_RED   2048
#define SM_SMAX  2112           // [128][4]
#define SM_SZ    4160
#define SM_SS    6208
#define SM_TILES 8448
#define OFF_A    0              // 128 rows * 144B = 18432
#define OFF_B    18432          // 256 rows * 144B = 36864
#define BUFSZ    55296
#define SMEM_TOTAL (SM_TILES + NSTG * BUFSZ)   // 174336

#define NEG_HUGE (-3.402823466e38f)

// Scratch (allocation-free rule: __device__ globals)
__device__ __half g_qh[BATCH * SEQ * HID];   // fp16(q_norm)
__device__ __half g_kh[BATCH * SEQ * HID];   // fp16(k_norm)
__device__ float  g_wd[SEQ];
__device__ float  g_invden[BATCH];

__device__ __forceinline__ uint32_t smem_u32(const void* p) {
    uint32_t a;
    asm("{ .reg .u64 t; cvta.to.shared.u64 t, %1; cvt.u32.u64 %0, t; }" : "=r"(a) : "l"(p));
    return a;
}

#define LDSM4(A, addr)                                                          \
    asm volatile("ldmatrix.sync.aligned.m8n8.x4.shared.b16 {%0,%1,%2,%3}, [%4];"\
        : "=r"((A)[0]), "=r"((A)[1]), "=r"((A)[2]), "=r"((A)[3]) : "r"(addr))

#define MMAH(acc, A, b0, b1)                                                    \
    asm volatile("mma.sync.aligned.m16n8k16.row.col.f32.f16.f16.f32 "           \
        "{%0,%1,%2,%3}, {%4,%5,%6,%7}, {%8,%9}, {%0,%1,%2,%3};"                 \
        : "+f"((acc)[0]), "+f"((acc)[1]), "+f"((acc)[2]), "+f"((acc)[3])        \
        : "r"((A)[0]), "r"((A)[1]), "r"((A)[2]), "r"((A)[3]), "r"(b0), "r"(b1))

#define CP16(d, s) \
    asm volatile("cp.async.cg.shared.global [%0], [%1], 16;" :: "r"(d), "l"(s) : "memory")
#define CPCOMMIT() asm volatile("cp.async.commit_group;" ::: "memory")
#define CPWAIT(n)  asm volatile("cp.async.wait_group %0;" :: "n"(n) : "memory")

// ---------------------------------------------------------------------------
// Kernel 1: L2-normalize q,k -> fp16; extra block (last) computes decay
// table + inverse denominators and zeroes the output accumulator.
// ---------------------------------------------------------------------------
__global__ void quant_kernel(const float* __restrict__ q,
                             const float* __restrict__ k,
                             const float* __restrict__ qmask,
                             const float* __restrict__ alpha_raw,
                             const float* __restrict__ logit_scale,
                             float* __restrict__ out) {
    int row = blockIdx.x;
    int t = threadIdx.x;

    if (row == 2 * BATCH * SEQ) {   // tables + output zeroing block
        float a = *alpha_raw;
        float alpha = (a > 20.f) ? a : log1pf(expf(a));
        float scale = expf(*logit_scale);
        g_wd[t] = scale * expf(-alpha * (float)t);
        if (t < BATCH) {
            float s = 0.f;
            for (int x = 0; x < SEQ; x++) s += qmask[t * SEQ + x];
            g_invden[t] = 1.0f / fmaxf(s, 1.0f);
        }
        out[t] = 0.f; out[t + 256] = 0.f; out[t + 512] = 0.f; out[t + 768] = 0.f;
        return;
    }

    const bool is_q = (row < BATCH * SEQ);
    int r = is_q ? row : row - BATCH * SEQ;
    const float* src = (is_q ? q : k) + (size_t)r * HID;
    __half* dh = (is_q ? g_qh : g_kh) + (size_t)r * HID;
    float v0 = src[t], v1 = src[t + 256], v2 = src[t + 512];
    float ss = v0 * v0 + v1 * v1 + v2 * v2;
#pragma unroll
    for (int o = 16; o > 0; o >>= 1) ss += __shfl_xor_sync(0xFFFFFFFFu, ss, o);
    __shared__ float sred[8];
    __shared__ float s_inv;
    if ((t & 31) == 0) sred[t >> 5] = ss;
    __syncthreads();
    if (t == 0) {
        float tot = 0.f;
#pragma unroll
        for (int w = 0; w < 8; w++) tot += sred[w];
        s_inv = 1.0f / fmaxf(sqrtf(tot), 1e-12f);
    }
    __syncthreads();
    float inv = s_inv;
    dh[t]       = __float2half(v0 * inv);
    dh[t + 256] = __float2half(v1 * inv);
    dh[t + 512] = __float2half(v2 * inv);
}

// ---------------------------------------------------------------------------
// Kernel 2: per-(pair, s-half) fp16 MMA GEMM sim = hq . hk, 128x256 tile,
// warp tile 32x64, 3-stage cp.async ring, one barrier per chunk, B fragments
// via ldmatrix.x4, fused decay + masked softmax epilogue, atomic out.
// ---------------------------------------------------------------------------
__global__ __launch_bounds__(NTP, 1)
void pair_kernel(const float* __restrict__ qmask,
                 const float* __restrict__ kmask,
                 float* __restrict__ out) {
    extern __shared__ char smem[];
    const uint32_t sb = smem_u32(smem);
    float* s_wd  = (float*)(smem + SM_WD);
    float* s_kv  = (float*)(smem + SM_KV);
    float* s_red = (float*)(smem + SM_RED);
    float* stg_max = (float*)(smem + SM_SMAX);
    float* stg_z   = (float*)(smem + SM_SZ);
    float* stg_s   = (float*)(smem + SM_SS);

    const int tid = threadIdx.x;
    const int w = tid >> 5, lane = tid & 31;
    const int wr = w >> 2, wc = w & 3;
    const int bx = blockIdx.x;
    const int pair = bx >> 1, shalf = bx & 1;
    const int i = pair >> 5, j = pair & 31;
    const int s0 = shalf * 128;

    const __half* Ag = g_qh + ((size_t)i * SEQ + s0) * HID;
    const __half* Bg = g_kh + (size_t)j * SEQ * HID;

    if (tid < SEQ) {
        s_wd[tid] = g_wd[tid];
        s_kv[tid] = (kmask[j * SEQ + tid] > 0.f) ? 1.f : 0.f;
    }

    float acc[2][8][4];
#pragma unroll
    for (int mi = 0; mi < 2; mi++)
#pragma unroll
        for (int ni = 0; ni < 8; ni++)
#pragma unroll
            for (int e = 0; e < 4; e++) acc[mi][ni][e] = 0.f;

    // cp.async one chunk (A 16KB + B 32KB) into stage cc%NSTG
    auto issue = [&](int cc) {
        const int kcol = cc * KC;
        const uint32_t tb = sb + SM_TILES + (cc % NSTG) * BUFSZ;
#pragma unroll
        for (int qq = 0; qq < 2; qq++) {   // A: 128 rows x 8 groups = 1024 x 16B
            int idx = qq * NTP + tid;
            int row = idx >> 3, g = idx & 7;
            CP16(tb + OFF_A + row * ROWB + g * 16,
                 Ag + (size_t)row * HID + kcol + g * 8);
        }
#pragma unroll
        for (int qq = 0; qq < 4; qq++) {   // B: 256 rows x 8 groups = 2048 x 16B
            int idx = qq * NTP + tid;
            int row = idx >> 3, g = idx & 7;
            CP16(tb + OFF_B + row * ROWB + g * 16,
                 Bg + (size_t)row * HID + kcol + g * 8);
        }
        CPCOMMIT();
    };

    issue(0);
    issue(1);

    // Loop-invariant per-lane ldmatrix offsets (within a stage buffer).
    // A (x4, 16x16): rows m = warp_m + (lane&15), k-half = (lane>>4)*16B
    uint32_t a_off[2];
#pragma unroll
    for (int mi = 0; mi < 2; mi++)
        a_off[mi] = OFF_A + (uint32_t)(wr * 32 + mi * 16 + (lane & 15)) * ROWB
                  + (lane >> 4) * 16;
    // B (x4 = two n8k16 tiles): rows n = n0 + (lane&7) + ((lane>>4)<<3),
    // k-half = ((lane>>3)&1)*16B
    uint32_t b_off[4];
#pragma unroll
    for (int p = 0; p < 4; p++)
        b_off[p] = OFF_B + (uint32_t)(wc * 64 + p * 16 + (lane & 7) + ((lane >> 4) << 3)) * ROWB
                 + ((lane >> 3) & 1) * 16;

    for (int cc = 0; cc < NCH; cc++) {
        CPWAIT(1);           // group cc complete (own thread)
        __syncthreads();     // visibility + all warps done with MMA(cc-1)
        if (cc + 2 < NCH) issue(cc + 2);   // overlaps MMA below

        const uint32_t tb = sb + SM_TILES + (cc % NSTG) * BUFSZ;
#pragma unroll
        for (int k16 = 0; k16 < 4; k16++) {
            const uint32_t ko = k16 * 32;
            uint32_t af[2][4];
            LDSM4(af[0], tb + a_off[0] + ko);
            LDSM4(af[1], tb + a_off[1] + ko);
#pragma unroll
            for (int p = 0; p < 4; p++) {
                uint32_t bf[4];
                LDSM4(bf, tb + b_off[p] + ko);
                MMAH(acc[0][2 * p],     af[0], bf[0], bf[1]);
                MMAH(acc[1][2 * p],     af[1], bf[0], bf[1]);
                MMAH(acc[0][2 * p + 1], af[0], bf[2], bf[3]);
                MMAH(acc[1][2 * p + 1], af[1], bf[2], bf[3]);
            }
        }
    }
    __syncthreads();   // last buffer consumed by all before epilogue smem reuse

    // ---- epilogue: decay + masked softmax over t, score = sum p*sim ------
    // Fast path: wd[0] = scale is the max decay weight and |sim| <= ~1.01,
    // so when scale <= 60 no exp can overflow -> skip the row-max stage.
    const bool fast = (s_wd[0] <= 60.0f);

    if (!fast) {
        // stage 1: per-row max over this warp's 64 cols
#pragma unroll
        for (int mi = 0; mi < 2; mi++)
#pragma unroll
            for (int q8 = 0; q8 < 2; q8++) {
                int r = wr * 32 + mi * 16 + q8 * 8 + (lane >> 2);
                int sg = s0 + r;
                float m = NEG_HUGE;
#pragma unroll
                for (int ni = 0; ni < 8; ni++)
#pragma unroll
                    for (int e = 0; e < 2; e++) {
                        int t = wc * 64 + ni * 8 + 2 * (lane & 3) + e;
                        float v = acc[mi][ni][q8 * 2 + e];
                        int d = sg - t; d = (d < 0) ? -d : d;
                        float l = v * s_wd[d];
                        if (s_kv[t] > 0.f) m = fmaxf(m, l);
                    }
                m = fmaxf(m, __shfl_xor_sync(0xFFFFFFFFu, m, 1));
                m = fmaxf(m, __shfl_xor_sync(0xFFFFFFFFu, m, 2));
                if ((lane & 3) == 0) stg_max[r * 4 + wc] = m;
            }
        __syncthreads();
    }

    // stage 2: exp-sum and weighted sim-sum
#pragma unroll
    for (int mi = 0; mi < 2; mi++)
#pragma unroll
        for (int q8 = 0; q8 < 2; q8++) {
            int r = wr * 32 + mi * 16 + q8 * 8 + (lane >> 2);
            int sg = s0 + r;
            float M = 0.f;
            bool mvalid = true;
            if (!fast) {
                M = fmaxf(fmaxf(stg_max[r * 4], stg_max[r * 4 + 1]),
                          fmaxf(stg_max[r * 4 + 2], stg_max[r * 4 + 3]));
                mvalid = (M > NEG_HUGE);
            }
            float Z = 0.f, S = 0.f;
#pragma unroll
            for (int ni = 0; ni < 8; ni++)
#pragma unroll
                for (int e = 0; e < 2; e++) {
                    int t = wc * 64 + ni * 8 + 2 * (lane & 3) + e;
                    float v = acc[mi][ni][q8 * 2 + e];
                    int d = sg - t; d = (d < 0) ? -d : d;
                    float l = v * s_wd[d];
                    float ex = (s_kv[t] > 0.f && mvalid) ? __expf(l - M) : 0.f;
                    Z += ex; S += ex * v;
                }
            Z += __shfl_xor_sync(0xFFFFFFFFu, Z, 1);
            Z += __shfl_xor_sync(0xFFFFFFFFu, Z, 2);
            S += __shfl_xor_sync(0xFFFFFFFFu, S, 1);
            S += __shfl_xor_sync(0xFFFFFFFFu, S, 2);
            if ((lane & 3) == 0) { stg_z[r * 4 + wc] = Z; stg_s[r * 4 + wc] = S; }
        }
    __syncthreads();

    // stage 3: combine warp-cols, apply q_mask, block-reduce, atomic out
    float val = 0.f;
    if (tid < 128) {
        int r = tid;
        float Z = stg_z[r * 4] + stg_z[r * 4 + 1] + stg_z[r * 4 + 2] + stg_z[r * 4 + 3];
        float S = stg_s[r * 4] + stg_s[r * 4 + 1] + stg_s[r * 4 + 2] + stg_s[r * 4 + 3];
        float sc = (Z > 0.f) ? (S / Z) : 0.f;
        val = sc * qmask[i * SEQ + s0 + r];
    }
#pragma unroll
    for (int o = 16; o > 0; o >>= 1) val += __shfl_xor_sync(0xFFFFFFFFu, val, o);
    if (tid < 128 && lane == 0) s_red[w] = val;
    __syncthreads();
    if (tid == 0) {
        float tot = s_red[0] + s_red[1] + s_red[2] + s_red[3];
        atomicAdd(&out[pair], tot * g_invden[i]);   // 2 commutative addends: deterministic
    }
}

// ---------------------------------------------------------------------------
extern "C" void kernel_launch(void* const* d_in, const int* in_sizes, int n_in,
                              void* d_out, int out_size) {
    const float* q  = (const float*)d_in[0];
    const float* k  = (const float*)d_in[1];
    const float* qm = (const float*)d_in[2];
    const float* km = (const float*)d_in[3];
    const float* ar = (const float*)d_in[4];
    const float* ls = (const float*)d_in[5];
    float* out = (float*)d_out;

    static int attr_done = 0;
    if (!attr_done) {
        cudaFuncSetAttribute(pair_kernel, cudaFuncAttributeMaxDynamicSharedMemorySize, SMEM_TOTAL);
        attr_done = 1;
    }

    quant_kernel<<<2 * BATCH * SEQ + 1, 256>>>(q, k, qm, ar, ls, out);
    pair_kernel<<<BATCH * BATCH * 2, NTP, SMEM_TOTAL>>>(qm, km, out);
}